// round 9
// baseline (speedup 1.0000x reference)
#include <cuda_runtime.h>
#include <cstdint>

#define NV 6890
#define NJ 24
#define NBD 10
#define NBATCH 256
#define NP 100

// GEMM tiling: C[6912 x 768] = U[6912 x 104] * MT^T (MT is [768 x 104])
#define MT_R 64          // rows (verts) per block
#define NT_C 48          // cols per block (= 16 batches)
#define KT 104           // padded K (96 real + 1 transl + 7 zero)
#define GM 108           // 108*64 = 6912 >= NV
#define GN 16            // 768/48

// scratch (allocation-free rule: __device__ globals)
__device__ float g_vshaped[NV * 3];
__device__ float g_joints[NJ * 3];
__device__ float g_A[NBATCH * NJ * 12];    // per (b,j): R row-major [0..8], t'[9..11] (for plane)
__device__ float g_U[GM * MT_R * KT];      // 6912 x 104, tf32-rounded
__device__ float g_MT[768 * KT];           // [n][k], tf32-rounded

__constant__ int c_parents[NJ] = {-1,0,0,0,1,2,3,4,5,6,7,8,9,9,9,12,13,14,16,17,18,19,20,21};
__constant__ int c_level[NJ]   = { 0,1,1,1,2,2,2,3,3,3,4,4,4,4, 4, 5, 5, 5, 6, 6, 7, 8, 9,10};

__device__ __forceinline__ float tf32r(float x) {
    uint32_t u;
    asm("cvt.rna.tf32.f32 %0, %1;" : "=r"(u) : "f"(x));
    return __uint_as_float(u);
}

// packed fp32x2 FMA helpers (plane path)
__device__ __forceinline__ void ffma2(unsigned long long& d, unsigned long long a, unsigned long long b) {
    asm("fma.rn.f32x2 %0, %1, %2, %0;" : "+l"(d) : "l"(a), "l"(b));
}
__device__ __forceinline__ unsigned long long bcast2(float w) {
    unsigned long long r;
    asm("mov.b64 %0, {%1, %1};" : "=l"(r) : "r"(__float_as_uint(w)));
    return r;
}
__device__ __forceinline__ float2 unpack2(unsigned long long p) {
    unsigned int lo, hi;
    asm("mov.b64 {%0, %1}, %2;" : "=r"(lo), "=r"(hi) : "l"(p));
    return make_float2(__uint_as_float(lo), __uint_as_float(hi));
}

#define MMA_TF32(d, a0, a1, a2, a3, b0, b1) \
    asm volatile("mma.sync.aligned.m16n8k8.row.col.f32.tf32.tf32.f32 " \
        "{%0,%1,%2,%3}, {%4,%5,%6,%7}, {%8,%9}, {%0,%1,%2,%3};" \
        : "+f"(d[0]), "+f"(d[1]), "+f"(d[2]), "+f"(d[3]) \
        : "r"(a0), "r"(a1), "r"(a2), "r"(a3), "r"(b0), "r"(b1))

// ---------------- kernel 1: v_shaped + zero joints ----------------
__global__ void k_prep(const float* __restrict__ vt, const float* __restrict__ sd,
                       const float* __restrict__ betas) {
    if (blockIdx.x == 0 && threadIdx.x < NJ * 3) g_joints[threadIdx.x] = 0.f;
    int i = blockIdx.x * 256 + threadIdx.x;
    if (i >= NV * 3) return;
    float acc = vt[i];
    #pragma unroll
    for (int l = 0; l < NBD; l++) acc += betas[1 + l] * sd[i * NBD + l];
    g_vshaped[i] = acc * betas[0];
}

// ---------------- kernel 2: joints (split-V atomics) + build U matrix ----------------
__global__ void __launch_bounds__(512) k_joints(const float* __restrict__ Jreg,
                                                const float* __restrict__ lbs) {
    int tid = threadIdx.x;
    if (blockIdx.y == 4) {
        // ---- build U: U[v][4j+k] = w[v,j]*(x,y,z,1)[k]; [96]=1; [97..103]=0 ----
        int v = blockIdx.x * 512 + tid;
        if (v >= GM * MT_R) return;
        float4 u[26];
        if (v < NV) {
            float x = g_vshaped[v*3], y = g_vshaped[v*3+1], z = g_vshaped[v*3+2];
            const float4* w4 = reinterpret_cast<const float4*>(lbs + (size_t)v * NJ);
            #pragma unroll
            for (int c = 0; c < 6; c++) {
                float4 q = w4[c];
                float ws[4] = {q.x, q.y, q.z, q.w};
                #pragma unroll
                for (int t = 0; t < 4; t++) {
                    float w = ws[t];
                    u[c*4 + t] = make_float4(tf32r(w*x), tf32r(w*y), tf32r(w*z), tf32r(w));
                }
            }
            u[24] = make_float4(1.f, 0.f, 0.f, 0.f);
            u[25] = make_float4(0.f, 0.f, 0.f, 0.f);
        } else {
            #pragma unroll
            for (int c = 0; c < 26; c++) u[c] = make_float4(0.f, 0.f, 0.f, 0.f);
        }
        float4* dst = reinterpret_cast<float4*>(g_U + (size_t)v * KT);
        #pragma unroll
        for (int c = 0; c < 26; c++) dst[c] = u[c];
        return;
    }
    // ---- joints ----
    int j = blockIdx.x;
    int chunk = blockIdx.y;
    const int CH = (NV + 3) / 4;
    int v0 = chunk * CH;
    int v1 = min(v0 + CH, NV);
    float s0 = 0.f, s1 = 0.f, s2 = 0.f;
    for (int v = v0 + tid; v < v1; v += 512) {
        float w = __ldg(Jreg + j * NV + v);
        s0 += w * g_vshaped[v * 3 + 0];
        s1 += w * g_vshaped[v * 3 + 1];
        s2 += w * g_vshaped[v * 3 + 2];
    }
    #pragma unroll
    for (int off = 16; off > 0; off >>= 1) {
        s0 += __shfl_xor_sync(0xffffffff, s0, off);
        s1 += __shfl_xor_sync(0xffffffff, s1, off);
        s2 += __shfl_xor_sync(0xffffffff, s2, off);
    }
    __shared__ float red[16][3];
    int wid = tid >> 5, lane = tid & 31;
    if (lane == 0) { red[wid][0] = s0; red[wid][1] = s1; red[wid][2] = s2; }
    __syncthreads();
    if (wid == 0 && lane < 16) {
        float r0 = red[lane][0], r1 = red[lane][1], r2 = red[lane][2];
        #pragma unroll
        for (int off = 8; off > 0; off >>= 1) {
            r0 += __shfl_xor_sync(0xffff, r0, off);
            r1 += __shfl_xor_sync(0xffff, r1, off);
            r2 += __shfl_xor_sync(0xffff, r2, off);
        }
        if (lane == 0) {
            atomicAdd(&g_joints[j * 3 + 0], r0);
            atomicAdd(&g_joints[j * 3 + 1], r1);
            atomicAdd(&g_joints[j * 3 + 2], r2);
        }
    }
}

// ---------------- kernel 3: kinematic chain -> g_A (fp32) + g_MT (tf32) ----------------
__global__ void k_chain(const float* __restrict__ pose_wo,
                        const float* __restrict__ rbk, const float* __restrict__ rfr,
                        const float* __restrict__ lbk, const float* __restrict__ lfr,
                        const float* __restrict__ go, const float* __restrict__ transl,
                        float* __restrict__ out_J) {
    int b = blockIdx.x;
    int j = threadIdx.x;   // blockDim = 32, joints use 0..23
    __shared__ float sT[NJ][12];
    __shared__ float sM[NJ][12];

    if (j < NJ) {
        float p0, p1, p2;
        if (j == 0)      { p0 = go[b*3]; p1 = go[b*3+1]; p2 = go[b*3+2]; }
        else if (j <= 6) { int o = b*57 + (j-1)*3; p0 = pose_wo[o]; p1 = pose_wo[o+1]; p2 = pose_wo[o+2]; }
        else if (j == 7) { p0 = lbk[b*3]; p1 = lbk[b*3+1]; p2 = lbk[b*3+2]; }
        else if (j == 8) { p0 = rbk[b*3]; p1 = rbk[b*3+1]; p2 = rbk[b*3+2]; }
        else if (j == 9) { int o = b*57 + 18; p0 = pose_wo[o]; p1 = pose_wo[o+1]; p2 = pose_wo[o+2]; }
        else if (j == 10){ p0 = lfr[b]; p1 = 0.f; p2 = 0.f; }
        else if (j == 11){ p0 = rfr[b]; p1 = 0.f; p2 = 0.f; }
        else             { int o = b*57 + 21 + (j-12)*3; p0 = pose_wo[o]; p1 = pose_wo[o+1]; p2 = pose_wo[o+2]; }

        float a0 = p0 + 1e-8f, a1 = p1 + 1e-8f, a2 = p2 + 1e-8f;
        float ang = sqrtf(a0*a0 + a1*a1 + a2*a2);
        float inv = 1.f / ang;
        float rx = p0 * inv, ry = p1 * inv, rz = p2 * inv;
        float sn, cs;
        __sincosf(ang, &sn, &cs);
        float omc = 1.f - cs;
        sT[j][0] = 1.f - omc * (ry*ry + rz*rz);
        sT[j][1] = -sn*rz + omc*rx*ry;
        sT[j][2] =  sn*ry + omc*rx*rz;
        sT[j][3] =  sn*rz + omc*rx*ry;
        sT[j][4] = 1.f - omc * (rx*rx + rz*rz);
        sT[j][5] = -sn*rx + omc*ry*rz;
        sT[j][6] = -sn*ry + omc*rx*rz;
        sT[j][7] =  sn*rx + omc*ry*rz;
        sT[j][8] = 1.f - omc * (rx*rx + ry*ry);

        int par = c_parents[j];
        float jx = g_joints[j*3], jy = g_joints[j*3+1], jz = g_joints[j*3+2];
        if (par < 0) { sT[j][9] = jx; sT[j][10] = jy; sT[j][11] = jz; }
        else {
            sT[j][9]  = jx - g_joints[par*3];
            sT[j][10] = jy - g_joints[par*3+1];
            sT[j][11] = jz - g_joints[par*3+2];
        }
    }
    __syncwarp();

    if (j == 0) {
        #pragma unroll
        for (int m = 0; m < 12; m++) sM[0][m] = sT[0][m];
    }
    __syncwarp();

    #pragma unroll
    for (int lvl = 1; lvl <= 10; lvl++) {
        if (j < NJ && c_level[j] == lvl) {
            int par = c_parents[j];
            const float* P = sM[par];
            const float* L = sT[j];
            float* M = sM[j];
            M[0] = P[0]*L[0] + P[1]*L[3] + P[2]*L[6];
            M[1] = P[0]*L[1] + P[1]*L[4] + P[2]*L[7];
            M[2] = P[0]*L[2] + P[1]*L[5] + P[2]*L[8];
            M[3] = P[3]*L[0] + P[4]*L[3] + P[5]*L[6];
            M[4] = P[3]*L[1] + P[4]*L[4] + P[5]*L[7];
            M[5] = P[3]*L[2] + P[4]*L[5] + P[5]*L[8];
            M[6] = P[6]*L[0] + P[7]*L[3] + P[8]*L[6];
            M[7] = P[6]*L[1] + P[7]*L[4] + P[8]*L[7];
            M[8] = P[6]*L[2] + P[7]*L[5] + P[8]*L[8];
            M[9]  = P[0]*L[9] + P[1]*L[10] + P[2]*L[11] + P[9];
            M[10] = P[3]*L[9] + P[4]*L[10] + P[5]*L[11] + P[10];
            M[11] = P[6]*L[9] + P[7]*L[10] + P[8]*L[11] + P[11];
        }
        __syncwarp();
    }

    if (j < NJ) {
        const float* M = sM[j];
        out_J[(b*NJ + j)*3 + 0] = M[9];
        out_J[(b*NJ + j)*3 + 1] = M[10];
        out_J[(b*NJ + j)*3 + 2] = M[11];

        float jx = g_joints[j*3], jy = g_joints[j*3+1], jz = g_joints[j*3+2];
        float tp[3];
        tp[0] = M[9]  - (M[0]*jx + M[1]*jy + M[2]*jz);
        tp[1] = M[10] - (M[3]*jx + M[4]*jy + M[5]*jz);
        tp[2] = M[11] - (M[6]*jx + M[7]*jy + M[8]*jz);

        float* Ao = g_A + (b*NJ + j) * 12;
        #pragma unroll
        for (int m = 0; m < 9; m++) Ao[m] = M[m];
        Ao[9] = tp[0]; Ao[10] = tp[1]; Ao[11] = tp[2];

        // M^T rows for GEMM: g_MT[(b*3+m)][4j+k]
        #pragma unroll
        for (int m = 0; m < 3; m++) {
            float* row = g_MT + (size_t)(b*3 + m) * KT + 4*j;
            row[0] = tf32r(M[m*3+0]);
            row[1] = tf32r(M[m*3+1]);
            row[2] = tf32r(M[m*3+2]);
            row[3] = tf32r(tp[m]);
        }
    }
    if (j == 0) {
        #pragma unroll
        for (int m = 0; m < 3; m++) {
            float* row = g_MT + (size_t)(b*3 + m) * KT;
            row[96] = tf32r(transl[b*3 + m]);
            #pragma unroll
            for (int k = 97; k < KT; k++) row[k] = 0.f;
        }
    }
}

// ---------------- kernel 4: tf32 tensor-core GEMM (verts only) ----------------
__global__ void __launch_bounds__(128, 4) k_gemm(float* __restrict__ out_verts) {
    __shared__ float sU[MT_R * KT];    // 26624 B (reused as sC[64][49] in epilogue)
    __shared__ float sB[NT_C * KT];    // 19968 B
    int tid = threadIdx.x;

    int v0 = blockIdx.x * MT_R;
    int n0 = blockIdx.y * NT_C;

    // load tiles (row stride 104 floats = 26 float4, contiguous across rows)
    {
        const float4* gU4 = reinterpret_cast<const float4*>(g_U);
        float4* sU4 = reinterpret_cast<float4*>(sU);
        #pragma unroll
        for (int i = 0; i < 13; i++) sU4[i*128 + tid] = gU4[(size_t)v0*26 + i*128 + tid];
        const float4* gB4 = reinterpret_cast<const float4*>(g_MT);
        float4* sB4 = reinterpret_cast<float4*>(sB);
        for (int lin = tid; lin < NT_C*26; lin += 128) sB4[lin] = gB4[(size_t)n0*26 + lin];
    }
    __syncthreads();

    int w = tid >> 5, lane = tid & 31;
    int gid = lane >> 2, tig = lane & 3;
    int r0 = w * 16 + gid;

    float acc[6][4];
    #pragma unroll
    for (int nf = 0; nf < 6; nf++)
        #pragma unroll
        for (int t = 0; t < 4; t++) acc[nf][t] = 0.f;

    #pragma unroll
    for (int ks = 0; ks < 13; ks++) {
        int k0 = ks * 8;
        uint32_t a0 = __float_as_uint(sU[(r0    ) * KT + k0 + tig    ]);
        uint32_t a1 = __float_as_uint(sU[(r0 + 8) * KT + k0 + tig    ]);
        uint32_t a2 = __float_as_uint(sU[(r0    ) * KT + k0 + tig + 4]);
        uint32_t a3 = __float_as_uint(sU[(r0 + 8) * KT + k0 + tig + 4]);
        #pragma unroll
        for (int nf = 0; nf < 6; nf++) {
            uint32_t b0 = __float_as_uint(sB[(nf*8 + gid) * KT + k0 + tig    ]);
            uint32_t b1 = __float_as_uint(sB[(nf*8 + gid) * KT + k0 + tig + 4]);
            MMA_TF32(acc[nf], a0, a1, a2, a3, b0, b1);
        }
    }
    __syncthreads();   // done reading sU; reuse as sC[64][49]

    float* sC = sU;
    #pragma unroll
    for (int nf = 0; nf < 6; nf++) {
        int c = nf*8 + 2*tig;
        sC[(r0    ) * 49 + c    ] = acc[nf][0];
        sC[(r0    ) * 49 + c + 1] = acc[nf][1];
        sC[(r0 + 8) * 49 + c    ] = acc[nf][2];
        sC[(r0 + 8) * 49 + c + 1] = acc[nf][3];
    }
    __syncthreads();

    int nrows = min(MT_R, NV - v0);
    int cnt = nrows * 3;
    int bbase = blockIdx.y * 16;
    // precompute the two (row, comp) pairs this thread handles
    int lin0 = tid, lin1 = tid + 128;
    int re0 = lin0 / 3, me0 = lin0 - re0 * 3;
    int re1 = lin1 / 3, me1 = lin1 - re1 * 3;
    bool ok0 = lin0 < cnt, ok1 = lin1 < cnt;
    const float* s0p = sC + re0 * 49 + me0;
    const float* s1p = sC + re1 * 49 + me1;
    float* ob = out_verts + ((size_t)bbase * NV + v0) * 3;
    #pragma unroll
    for (int bloc = 0; bloc < 16; bloc++) {
        float* o = ob + (size_t)bloc * NV * 3;
        if (ok0) o[lin0] = s0p[bloc * 3];
        if (ok1) o[lin1] = s1p[bloc * 3];
    }
}

// ---------------- kernel 5: plane points (standalone, one batch per block) ----------------
__global__ void __launch_bounds__(128) k_plane(const float* __restrict__ lbs,
                       const float* __restrict__ transl,
                       const int* __restrict__ bl, const int* __restrict__ fl,
                       const int* __restrict__ br, const int* __restrict__ fr,
                       const float* __restrict__ ipbl, const float* __restrict__ ipfl,
                       const float* __restrict__ ipbr, const float* __restrict__ ipfr,
                       float* __restrict__ out_plane) {
    int b = blockIdx.x;
    int tid = threadIdx.x;
    __shared__ float sP[NJ * 12];
    if (tid < 72) reinterpret_cast<float4*>(sP)[tid] =
        reinterpret_cast<const float4*>(g_A)[b * 72 + tid];
    __syncthreads();
    const ulonglong2* sA2 = reinterpret_cast<const ulonglong2*>(sP);
    float t0 = __ldg(transl + b*3), t1 = __ldg(transl + b*3+1), t2 = __ldg(transl + b*3+2);
    for (int p = tid; p < 4 * NP; p += 128) {
        int s = p / NP, l = p % NP;
        const int* ids = (s == 0) ? bl : (s == 1) ? fl : (s == 2) ? br : fr;
        const float* ip = (s == 0) ? ipbl : (s == 1) ? ipfl : (s == 2) ? ipbr : ipfr;
        int v = ids[l];
        unsigned long long A0[6];
        #pragma unroll
        for (int m = 0; m < 6; m++) A0[m] = 0ull;
        const float4* w4 = reinterpret_cast<const float4*>(lbs + (size_t)v * NJ);
        #pragma unroll
        for (int c = 0; c < 6; c++) {
            float4 wq = w4[c];
            float ws[4] = {wq.x, wq.y, wq.z, wq.w};
            #pragma unroll
            for (int q = 0; q < 4; q++) {
                int j = c * 4 + q;
                ulonglong2 p0 = sA2[j*3+0], p1 = sA2[j*3+1], p2 = sA2[j*3+2];
                unsigned long long wp = bcast2(ws[q]);
                ffma2(A0[0], wp, p0.x); ffma2(A0[1], wp, p0.y);
                ffma2(A0[2], wp, p1.x); ffma2(A0[3], wp, p1.y);
                ffma2(A0[4], wp, p2.x); ffma2(A0[5], wp, p2.y);
            }
        }
        float2 T01 = unpack2(A0[0]), T23 = unpack2(A0[1]), T45 = unpack2(A0[2]);
        float2 T67 = unpack2(A0[3]), T89 = unpack2(A0[4]), Tab = unpack2(A0[5]);
        const float* pt = ip + ((size_t)b * NP + l) * 3;
        float x = pt[0], y = pt[1], z = pt[2];
        float* o = out_plane + ((size_t)b * 4 * NP + p) * 3;
        o[0] = T01.x*x + T01.y*y + T23.x*z + T89.y + t0;
        o[1] = T23.y*x + T45.x*y + T45.y*z + Tab.x + t1;
        o[2] = T67.x*x + T67.y*y + T89.x*z + Tab.y + t2;
    }
}

extern "C" void kernel_launch(void* const* d_in, const int* in_sizes, int n_in,
                              void* d_out, int out_size) {
    const float* v_template = (const float*)d_in[0];
    const float* shapedirs  = (const float*)d_in[1];
    const float* J_regressor= (const float*)d_in[2];
    const float* lbs        = (const float*)d_in[3];
    const float* betas      = (const float*)d_in[4];
    const float* pose_wo    = (const float*)d_in[5];
    const float* rbk        = (const float*)d_in[6];
    const float* rfr        = (const float*)d_in[7];
    const float* lbk        = (const float*)d_in[8];
    const float* lfr        = (const float*)d_in[9];
    const float* transl     = (const float*)d_in[10];
    const float* go         = (const float*)d_in[11];
    const float* ipbl       = (const float*)d_in[12];
    const float* ipfl       = (const float*)d_in[13];
    const float* ipbr       = (const float*)d_in[14];
    const float* ipfr       = (const float*)d_in[15];
    // d_in[16] = parents (int64) — hardcoded in c_parents
    const int* bl = (const int*)d_in[17];
    const int* br = (const int*)d_in[18];
    const int* fl = (const int*)d_in[19];
    const int* fr = (const int*)d_in[20];

    float* out = (float*)d_out;
    float* out_verts = out;                                   // B*NV*3
    float* out_J     = out + (size_t)NBATCH * NV * 3;         // B*NJ*3
    float* out_plane = out_J + (size_t)NBATCH * NJ * 3;       // B*4P*3

    k_prep<<<81, 256>>>(v_template, shapedirs, betas);

    dim3 gj(NJ, 5);
    k_joints<<<gj, 512>>>(J_regressor, lbs);

    k_chain<<<NBATCH, 32>>>(pose_wo, rbk, rfr, lbk, lfr, go, transl, out_J);

    k_plane<<<NBATCH, 128>>>(lbs, transl, bl, fl, br, fr, ipbl, ipfl, ipbr, ipfr, out_plane);

    dim3 gg(GM, GN);
    k_gemm<<<gg, 128>>>(out_verts);
}

// round 11
// speedup vs baseline: 1.8672x; 1.8672x over previous
#include <cuda_runtime.h>
#include <cstdint>

#define NV 6890
#define NJ 24
#define NBD 10
#define NBATCH 256
#define NP 100

// GEMM tiling: C[6912 x 768] = U[6912 x 104] * MT^T (MT is [768 x 104])
#define MT_R 64          // rows (verts) per block
#define NT_C 48          // cols per block (= 16 batches)
#define KT 104           // padded K (96 real + 1 transl + 7 zero)
#define KS 108           // smem row stride in floats (conflict-free: 12*gid+tig distinct mod 32)
#define GM 108           // 108*64 = 6912 >= NV
#define GN 16            // 768/48

// scratch (allocation-free rule: __device__ globals)
__device__ float g_vshaped[NV * 3];
__device__ float g_joints[NJ * 3];
__device__ float g_A[NBATCH * NJ * 12];    // per (b,j): R row-major [0..8], t'[9..11] (for plane)
__device__ float g_U[GM * MT_R * KT];      // 6912 x 104, tf32-rounded
__device__ float g_MT[768 * KT];           // [n][k], tf32-rounded

__constant__ int c_parents[NJ] = {-1,0,0,0,1,2,3,4,5,6,7,8,9,9,9,12,13,14,16,17,18,19,20,21};
__constant__ int c_level[NJ]   = { 0,1,1,1,2,2,2,3,3,3,4,4,4,4, 4, 5, 5, 5, 6, 6, 7, 8, 9,10};

__device__ __forceinline__ float tf32r(float x) {
    uint32_t u;
    asm("cvt.rna.tf32.f32 %0, %1;" : "=r"(u) : "f"(x));
    return __uint_as_float(u);
}

#define MMA_TF32(d, a0, a1, a2, a3, b0, b1) \
    asm volatile("mma.sync.aligned.m16n8k8.row.col.f32.tf32.tf32.f32 " \
        "{%0,%1,%2,%3}, {%4,%5,%6,%7}, {%8,%9}, {%0,%1,%2,%3};" \
        : "+f"(d[0]), "+f"(d[1]), "+f"(d[2]), "+f"(d[3]) \
        : "r"(a0), "r"(a1), "r"(a2), "r"(a3), "r"(b0), "r"(b1))

// ---------------- kernel 1: v_shaped + zero joints ----------------
__global__ void k_prep(const float* __restrict__ vt, const float* __restrict__ sd,
                       const float* __restrict__ betas) {
    if (blockIdx.x == 0 && threadIdx.x < NJ * 3) g_joints[threadIdx.x] = 0.f;
    int i = blockIdx.x * 256 + threadIdx.x;
    if (i >= NV * 3) return;
    float acc = vt[i];
    #pragma unroll
    for (int l = 0; l < NBD; l++) acc += betas[1 + l] * sd[i * NBD + l];
    g_vshaped[i] = acc * betas[0];
}

// ---------------- kernel 2: joints (split-V atomics) + build U matrix ----------------
__global__ void __launch_bounds__(512) k_joints(const float* __restrict__ Jreg,
                                                const float* __restrict__ lbs) {
    int tid = threadIdx.x;
    if (blockIdx.y == 4) {
        // ---- build U: U[v][4j+k] = w[v,j]*(x,y,z,1)[k]; [96]=1; [97..103]=0 ----
        int v = blockIdx.x * 512 + tid;
        if (v >= GM * MT_R) return;
        float4 u[26];
        if (v < NV) {
            float x = g_vshaped[v*3], y = g_vshaped[v*3+1], z = g_vshaped[v*3+2];
            const float4* w4 = reinterpret_cast<const float4*>(lbs + (size_t)v * NJ);
            #pragma unroll
            for (int c = 0; c < 6; c++) {
                float4 q = w4[c];
                float ws[4] = {q.x, q.y, q.z, q.w};
                #pragma unroll
                for (int t = 0; t < 4; t++) {
                    float w = ws[t];
                    u[c*4 + t] = make_float4(tf32r(w*x), tf32r(w*y), tf32r(w*z), tf32r(w));
                }
            }
            u[24] = make_float4(1.f, 0.f, 0.f, 0.f);
            u[25] = make_float4(0.f, 0.f, 0.f, 0.f);
        } else {
            #pragma unroll
            for (int c = 0; c < 26; c++) u[c] = make_float4(0.f, 0.f, 0.f, 0.f);
        }
        float4* dst = reinterpret_cast<float4*>(g_U + (size_t)v * KT);
        #pragma unroll
        for (int c = 0; c < 26; c++) dst[c] = u[c];
        return;
    }
    // ---- joints ----
    int j = blockIdx.x;
    int chunk = blockIdx.y;
    const int CH = (NV + 3) / 4;
    int v0 = chunk * CH;
    int v1 = min(v0 + CH, NV);
    float s0 = 0.f, s1 = 0.f, s2 = 0.f;
    for (int v = v0 + tid; v < v1; v += 512) {
        float w = __ldg(Jreg + j * NV + v);
        s0 += w * g_vshaped[v * 3 + 0];
        s1 += w * g_vshaped[v * 3 + 1];
        s2 += w * g_vshaped[v * 3 + 2];
    }
    #pragma unroll
    for (int off = 16; off > 0; off >>= 1) {
        s0 += __shfl_xor_sync(0xffffffff, s0, off);
        s1 += __shfl_xor_sync(0xffffffff, s1, off);
        s2 += __shfl_xor_sync(0xffffffff, s2, off);
    }
    __shared__ float red[16][3];
    int wid = tid >> 5, lane = tid & 31;
    if (lane == 0) { red[wid][0] = s0; red[wid][1] = s1; red[wid][2] = s2; }
    __syncthreads();
    if (wid == 0 && lane < 16) {
        float r0 = red[lane][0], r1 = red[lane][1], r2 = red[lane][2];
        #pragma unroll
        for (int off = 8; off > 0; off >>= 1) {
            r0 += __shfl_xor_sync(0xffff, r0, off);
            r1 += __shfl_xor_sync(0xffff, r1, off);
            r2 += __shfl_xor_sync(0xffff, r2, off);
        }
        if (lane == 0) {
            atomicAdd(&g_joints[j * 3 + 0], r0);
            atomicAdd(&g_joints[j * 3 + 1], r1);
            atomicAdd(&g_joints[j * 3 + 2], r2);
        }
    }
}

// ---------------- kernel 3: kinematic chain -> g_A (fp32) + g_MT (tf32) ----------------
__global__ void k_chain(const float* __restrict__ pose_wo,
                        const float* __restrict__ rbk, const float* __restrict__ rfr,
                        const float* __restrict__ lbk, const float* __restrict__ lfr,
                        const float* __restrict__ go, const float* __restrict__ transl,
                        float* __restrict__ out_J) {
    int b = blockIdx.x;
    int j = threadIdx.x;   // blockDim = 32, joints use 0..23
    __shared__ float sT[NJ][12];
    __shared__ float sM[NJ][12];

    if (j < NJ) {
        float p0, p1, p2;
        if (j == 0)      { p0 = go[b*3]; p1 = go[b*3+1]; p2 = go[b*3+2]; }
        else if (j <= 6) { int o = b*57 + (j-1)*3; p0 = pose_wo[o]; p1 = pose_wo[o+1]; p2 = pose_wo[o+2]; }
        else if (j == 7) { p0 = lbk[b*3]; p1 = lbk[b*3+1]; p2 = lbk[b*3+2]; }
        else if (j == 8) { p0 = rbk[b*3]; p1 = rbk[b*3+1]; p2 = rbk[b*3+2]; }
        else if (j == 9) { int o = b*57 + 18; p0 = pose_wo[o]; p1 = pose_wo[o+1]; p2 = pose_wo[o+2]; }
        else if (j == 10){ p0 = lfr[b]; p1 = 0.f; p2 = 0.f; }
        else if (j == 11){ p0 = rfr[b]; p1 = 0.f; p2 = 0.f; }
        else             { int o = b*57 + 21 + (j-12)*3; p0 = pose_wo[o]; p1 = pose_wo[o+1]; p2 = pose_wo[o+2]; }

        float a0 = p0 + 1e-8f, a1 = p1 + 1e-8f, a2 = p2 + 1e-8f;
        float ang = sqrtf(a0*a0 + a1*a1 + a2*a2);
        float inv = 1.f / ang;
        float rx = p0 * inv, ry = p1 * inv, rz = p2 * inv;
        float sn, cs;
        __sincosf(ang, &sn, &cs);
        float omc = 1.f - cs;
        sT[j][0] = 1.f - omc * (ry*ry + rz*rz);
        sT[j][1] = -sn*rz + omc*rx*ry;
        sT[j][2] =  sn*ry + omc*rx*rz;
        sT[j][3] =  sn*rz + omc*rx*ry;
        sT[j][4] = 1.f - omc * (rx*rx + rz*rz);
        sT[j][5] = -sn*rx + omc*ry*rz;
        sT[j][6] = -sn*ry + omc*rx*rz;
        sT[j][7] =  sn*rx + omc*ry*rz;
        sT[j][8] = 1.f - omc * (rx*rx + ry*ry);

        int par = c_parents[j];
        float jx = g_joints[j*3], jy = g_joints[j*3+1], jz = g_joints[j*3+2];
        if (par < 0) { sT[j][9] = jx; sT[j][10] = jy; sT[j][11] = jz; }
        else {
            sT[j][9]  = jx - g_joints[par*3];
            sT[j][10] = jy - g_joints[par*3+1];
            sT[j][11] = jz - g_joints[par*3+2];
        }
    }
    __syncwarp();

    if (j == 0) {
        #pragma unroll
        for (int m = 0; m < 12; m++) sM[0][m] = sT[0][m];
    }
    __syncwarp();

    #pragma unroll
    for (int lvl = 1; lvl <= 10; lvl++) {
        if (j < NJ && c_level[j] == lvl) {
            int par = c_parents[j];
            const float* P = sM[par];
            const float* L = sT[j];
            float* M = sM[j];
            M[0] = P[0]*L[0] + P[1]*L[3] + P[2]*L[6];
            M[1] = P[0]*L[1] + P[1]*L[4] + P[2]*L[7];
            M[2] = P[0]*L[2] + P[1]*L[5] + P[2]*L[8];
            M[3] = P[3]*L[0] + P[4]*L[3] + P[5]*L[6];
            M[4] = P[3]*L[1] + P[4]*L[4] + P[5]*L[7];
            M[5] = P[3]*L[2] + P[4]*L[5] + P[5]*L[8];
            M[6] = P[6]*L[0] + P[7]*L[3] + P[8]*L[6];
            M[7] = P[6]*L[1] + P[7]*L[4] + P[8]*L[7];
            M[8] = P[6]*L[2] + P[7]*L[5] + P[8]*L[8];
            M[9]  = P[0]*L[9] + P[1]*L[10] + P[2]*L[11] + P[9];
            M[10] = P[3]*L[9] + P[4]*L[10] + P[5]*L[11] + P[10];
            M[11] = P[6]*L[9] + P[7]*L[10] + P[8]*L[11] + P[11];
        }
        __syncwarp();
    }

    if (j < NJ) {
        const float* M = sM[j];
        out_J[(b*NJ + j)*3 + 0] = M[9];
        out_J[(b*NJ + j)*3 + 1] = M[10];
        out_J[(b*NJ + j)*3 + 2] = M[11];

        float jx = g_joints[j*3], jy = g_joints[j*3+1], jz = g_joints[j*3+2];
        float tp[3];
        tp[0] = M[9]  - (M[0]*jx + M[1]*jy + M[2]*jz);
        tp[1] = M[10] - (M[3]*jx + M[4]*jy + M[5]*jz);
        tp[2] = M[11] - (M[6]*jx + M[7]*jy + M[8]*jz);

        float* Ao = g_A + (b*NJ + j) * 12;
        #pragma unroll
        for (int m = 0; m < 9; m++) Ao[m] = M[m];
        Ao[9] = tp[0]; Ao[10] = tp[1]; Ao[11] = tp[2];

        // M^T rows for GEMM: g_MT[(b*3+m)][4j+k]
        #pragma unroll
        for (int m = 0; m < 3; m++) {
            float* row = g_MT + (size_t)(b*3 + m) * KT + 4*j;
            row[0] = tf32r(M[m*3+0]);
            row[1] = tf32r(M[m*3+1]);
            row[2] = tf32r(M[m*3+2]);
            row[3] = tf32r(tp[m]);
        }
    }
    if (j == 0) {
        #pragma unroll
        for (int m = 0; m < 3; m++) {
            float* row = g_MT + (size_t)(b*3 + m) * KT;
            row[96] = tf32r(transl[b*3 + m]);
            #pragma unroll
            for (int k = 97; k < KT; k++) row[k] = 0.f;
        }
    }
}

// ---------------- kernel 4: tf32 tensor-core GEMM (verts only) ----------------
__global__ void __launch_bounds__(128) k_gemm(float* __restrict__ out_verts) {
    __shared__ float sU[MT_R * KS];    // 27648 B (reused as sC[64][49] in epilogue)
    __shared__ float sB[NT_C * KS];    // 20736 B  (total 48384 <= 49152)
    int tid = threadIdx.x;

    int v0 = blockIdx.x * MT_R;
    int n0 = blockIdx.y * NT_C;

    // load tiles: global rows are 26 float4 (stride 104 floats); smem rows stride 27 float4 (108)
    {
        const float4* gU4 = reinterpret_cast<const float4*>(g_U);
        float4* sU4 = reinterpret_cast<float4*>(sU);
        #pragma unroll
        for (int i = 0; i < 13; i++) {
            int lin = i * 128 + tid;
            int r = lin / 26, c = lin - r * 26;
            sU4[r * 27 + c] = gU4[(size_t)(v0 + r) * 26 + c];
        }
        const float4* gB4 = reinterpret_cast<const float4*>(g_MT);
        float4* sB4 = reinterpret_cast<float4*>(sB);
        for (int lin = tid; lin < NT_C * 26; lin += 128) {
            int r = lin / 26, c = lin - r * 26;
            sB4[r * 27 + c] = gB4[(size_t)(n0 + r) * 26 + c];
        }
    }
    __syncthreads();

    int w = tid >> 5, lane = tid & 31;
    int gid = lane >> 2, tig = lane & 3;
    int r0 = w * 16 + gid;

    float acc[6][4];
    #pragma unroll
    for (int nf = 0; nf < 6; nf++)
        #pragma unroll
        for (int t = 0; t < 4; t++) acc[nf][t] = 0.f;

    const float* pa0 = sU + (r0    ) * KS + tig;
    const float* pa1 = sU + (r0 + 8) * KS + tig;
    const float* pb  = sB + gid * KS + tig;

    #pragma unroll 1
    for (int ks = 0; ks < 13; ks++) {
        int k0 = ks * 8;
        uint32_t a0 = __float_as_uint(pa0[k0    ]);
        uint32_t a1 = __float_as_uint(pa1[k0    ]);
        uint32_t a2 = __float_as_uint(pa0[k0 + 4]);
        uint32_t a3 = __float_as_uint(pa1[k0 + 4]);
        #pragma unroll
        for (int nf = 0; nf < 6; nf++) {
            uint32_t b0 = __float_as_uint(pb[nf * 8 * KS + k0    ]);
            uint32_t b1 = __float_as_uint(pb[nf * 8 * KS + k0 + 4]);
            MMA_TF32(acc[nf], a0, a1, a2, a3, b0, b1);
        }
    }
    __syncthreads();   // done reading sU; reuse as sC[64][49]

    float* sC = sU;
    #pragma unroll
    for (int nf = 0; nf < 6; nf++) {
        int c = nf*8 + 2*tig;
        sC[(r0    ) * 49 + c    ] = acc[nf][0];
        sC[(r0    ) * 49 + c + 1] = acc[nf][1];
        sC[(r0 + 8) * 49 + c    ] = acc[nf][2];
        sC[(r0 + 8) * 49 + c + 1] = acc[nf][3];
    }
    __syncthreads();

    int nrows = min(MT_R, NV - v0);
    int cnt = nrows * 3;
    int bbase = blockIdx.y * 16;
    int lin0 = tid, lin1 = tid + 128;
    int re0 = lin0 / 3, me0 = lin0 - re0 * 3;
    int re1 = lin1 / 3, me1 = lin1 - re1 * 3;
    bool ok0 = lin0 < cnt, ok1 = lin1 < cnt;
    const float* s0p = sC + re0 * 49 + me0;
    const float* s1p = sC + re1 * 49 + me1;
    float* ob = out_verts + ((size_t)bbase * NV + v0) * 3;
    #pragma unroll 1
    for (int bloc = 0; bloc < 16; bloc++) {
        float* o = ob + (size_t)bloc * NV * 3;
        if (ok0) o[lin0] = s0p[bloc * 3];
        if (ok1) o[lin1] = s1p[bloc * 3];
    }
}

// ---------------- kernel 5: plane points (scalar, one point/thread) ----------------
__global__ void __launch_bounds__(416) k_plane(const float* __restrict__ lbs,
                       const float* __restrict__ transl,
                       const int* __restrict__ bl, const int* __restrict__ fl,
                       const int* __restrict__ br, const int* __restrict__ fr,
                       const float* __restrict__ ipbl, const float* __restrict__ ipfl,
                       const float* __restrict__ ipbr, const float* __restrict__ ipfr,
                       float* __restrict__ out_plane) {
    int b = blockIdx.x;
    int tid = threadIdx.x;
    __shared__ float sP[NJ * 12];
    if (tid < 72) reinterpret_cast<float4*>(sP)[tid] =
        reinterpret_cast<const float4*>(g_A)[b * 72 + tid];
    __syncthreads();
    if (tid >= 4 * NP) return;
    int s = tid / NP, l = tid - s * NP;
    const int* ids = (s == 0) ? bl : (s == 1) ? fl : (s == 2) ? br : fr;
    const float* ip = (s == 0) ? ipbl : (s == 1) ? ipfl : (s == 2) ? ipbr : ipfr;
    int v = ids[l];

    float T[12];
    #pragma unroll
    for (int m = 0; m < 12; m++) T[m] = 0.f;
    const float4* w4 = reinterpret_cast<const float4*>(lbs + (size_t)v * NJ);
    #pragma unroll
    for (int c = 0; c < 6; c++) {
        float4 wq = w4[c];
        float ws[4] = {wq.x, wq.y, wq.z, wq.w};
        #pragma unroll
        for (int q = 0; q < 4; q++) {
            const float* a = sP + (c * 4 + q) * 12;
            float wv = ws[q];
            #pragma unroll
            for (int m = 0; m < 12; m++) T[m] += wv * a[m];
        }
    }
    const float* pt = ip + ((size_t)b * NP + l) * 3;
    float x = pt[0], y = pt[1], z = pt[2];
    float t0 = __ldg(transl + b*3), t1 = __ldg(transl + b*3+1), t2 = __ldg(transl + b*3+2);
    float* o = out_plane + ((size_t)b * 4 * NP + tid) * 3;
    o[0] = T[0]*x + T[1]*y + T[2]*z + T[9]  + t0;
    o[1] = T[3]*x + T[4]*y + T[5]*z + T[10] + t1;
    o[2] = T[6]*x + T[7]*y + T[8]*z + T[11] + t2;
}

extern "C" void kernel_launch(void* const* d_in, const int* in_sizes, int n_in,
                              void* d_out, int out_size) {
    const float* v_template = (const float*)d_in[0];
    const float* shapedirs  = (const float*)d_in[1];
    const float* J_regressor= (const float*)d_in[2];
    const float* lbs        = (const float*)d_in[3];
    const float* betas      = (const float*)d_in[4];
    const float* pose_wo    = (const float*)d_in[5];
    const float* rbk        = (const float*)d_in[6];
    const float* rfr        = (const float*)d_in[7];
    const float* lbk        = (const float*)d_in[8];
    const float* lfr        = (const float*)d_in[9];
    const float* transl     = (const float*)d_in[10];
    const float* go         = (const float*)d_in[11];
    const float* ipbl       = (const float*)d_in[12];
    const float* ipfl       = (const float*)d_in[13];
    const float* ipbr       = (const float*)d_in[14];
    const float* ipfr       = (const float*)d_in[15];
    // d_in[16] = parents (int64) — hardcoded in c_parents
    const int* bl = (const int*)d_in[17];
    const int* br = (const int*)d_in[18];
    const int* fl = (const int*)d_in[19];
    const int* fr = (const int*)d_in[20];

    float* out = (float*)d_out;
    float* out_verts = out;                                   // B*NV*3
    float* out_J     = out + (size_t)NBATCH * NV * 3;         // B*NJ*3
    float* out_plane = out_J + (size_t)NBATCH * NJ * 3;       // B*4P*3

    k_prep<<<81, 256>>>(v_template, shapedirs, betas);

    dim3 gj(NJ, 5);
    k_joints<<<gj, 512>>>(J_regressor, lbs);

    k_chain<<<NBATCH, 32>>>(pose_wo, rbk, rfr, lbk, lfr, go, transl, out_J);

    k_plane<<<NBATCH, 416>>>(lbs, transl, bl, fl, br, fr, ipbl, ipfl, ipbr, ipfr, out_plane);

    dim3 gg(GM, GN);
    k_gemm<<<gg, 128>>>(out_verts);
}